// round 1
// baseline (speedup 1.0000x reference)
#include <cuda_runtime.h>
#include <math.h>

// ---------------- problem constants ----------------
#define BB   8
#define NN   8192
#define SS   2048
#define C1   128
#define C2   256
#define TT   256
#define CIN  384
#define PP   65536      // B*N
#define MM   256        // output channels of both convs

// ---------------- device scratch (allowed: static __device__ arrays) -------
__device__ float g_X0[(size_t)CIN * PP];   // conv1 input [c][p]; reused for preact2
__device__ float g_Y [(size_t)MM  * PP];   // preact1 [o][p]; becomes X1 in place
__device__ float g_p2t[(size_t)BB * SS * C2]; // points2 transposed (b,s,c)
__device__ int   g_idx[PP * 3];
__device__ float g_wt [PP * 3];
__device__ float g_bias1[BB * MM];
__device__ float g_bias2[BB * MM];
__device__ float g_m1[MM], g_v1[MM], g_m2[MM], g_v2[MM];

__device__ __forceinline__ float gelu_exact(float x) {
    return 0.5f * x * (1.0f + erff(x * 0.70710678118654752440f));
}

// ---------------- time-conditioning biases ----------------
// bias1[b][o] = b_c1[o] + sum_c w_c1[o][c] * (gelu(t)@w_t1^T + b_t1)[b][c]
__global__ void te_bias_kernel(const float* __restrict__ t_embed,
                               const float* __restrict__ w_t1, const float* __restrict__ b_t1,
                               const float* __restrict__ w_c1, const float* __restrict__ b_c1,
                               const float* __restrict__ w_t2, const float* __restrict__ b_t2,
                               const float* __restrict__ w_c2, const float* __restrict__ b_c2) {
    __shared__ float ge[TT];
    __shared__ float te1[CIN];
    __shared__ float te2[MM];
    int b = blockIdx.x;
    int t = threadIdx.x;          // 0..383
    if (t < TT) ge[t] = gelu_exact(t_embed[b * TT + t]);
    __syncthreads();
    {   // te1: all 384 threads
        float a = b_t1[t];
        const float* w = w_t1 + (size_t)t * TT;
        #pragma unroll 4
        for (int c = 0; c < TT; c++) a += ge[c] * w[c];
        te1[t] = a;
    }
    if (t < MM) {
        float a = b_t2[t];
        const float* w = w_t2 + (size_t)t * TT;
        #pragma unroll 4
        for (int c = 0; c < TT; c++) a += ge[c] * w[c];
        te2[t] = a;
    }
    __syncthreads();
    if (t < MM) {
        float a = b_c1[t];
        const float* w = w_c1 + (size_t)t * CIN;
        #pragma unroll 4
        for (int c = 0; c < CIN; c++) a += te1[c] * w[c];
        g_bias1[b * MM + t] = a;

        float a2 = b_c2[t];
        const float* w2 = w_c2 + (size_t)t * MM;
        #pragma unroll 4
        for (int c = 0; c < MM; c++) a2 += te2[c] * w2[c];
        g_bias2[b * MM + t] = a2;
    }
}

// ---------------- 3-NN (fused distance + top-3) ----------------
__global__ __launch_bounds__(256) void knn_kernel(const float* __restrict__ xyz1,
                                                  const float* __restrict__ xyz2) {
    __shared__ float sx[SS], sy[SS], sz[SS], sn2[SS];
    int b = blockIdx.y;
    int n = blockIdx.x * 256 + threadIdx.x;
    const float* p2 = xyz2 + (size_t)b * SS * 3;
    for (int s = threadIdx.x; s < SS; s += 256) {
        float x = p2[s * 3 + 0], y = p2[s * 3 + 1], z = p2[s * 3 + 2];
        sx[s] = x; sy[s] = y; sz[s] = z;
        sn2[s] = x * x + y * y + z * z;
    }
    __syncthreads();
    const float* p1 = xyz1 + ((size_t)b * NN + n) * 3;
    float px = p1[0], py = p1[1], pz = p1[2];
    float n1 = px * px + py * py + pz * pz;

    float d0 = 1e30f, d1 = 1e30f, d2 = 1e30f;
    int   i0 = 0, i1 = 0, i2 = 0;
    for (int s = 0; s < SS; s++) {
        float t = px * sx[s];
        t = fmaf(py, sy[s], t);
        t = fmaf(pz, sz[s], t);
        float d = n1 + sn2[s] - 2.0f * t;   // same expansion as reference
        if (d < d2) {
            if (d < d0)      { d2 = d1; i2 = i1; d1 = d0; i1 = i0; d0 = d; i0 = s; }
            else if (d < d1) { d2 = d1; i2 = i1; d1 = d; i1 = s; }
            else             { d2 = d; i2 = s; }
        }
    }
    float r0 = 1.0f / (d0 + 1e-8f);
    float r1 = 1.0f / (d1 + 1e-8f);
    float r2 = 1.0f / (d2 + 1e-8f);
    float inv = 1.0f / (r0 + r1 + r2);
    int base = (b * NN + n) * 3;
    g_idx[base + 0] = i0; g_idx[base + 1] = i1; g_idx[base + 2] = i2;
    g_wt [base + 0] = r0 * inv; g_wt [base + 1] = r1 * inv; g_wt [base + 2] = r2 * inv;
}

// ---------------- transpose points2 (B,C2,S) -> (B,S,C2) ----------------
__global__ void transpose_p2(const float* __restrict__ points2) {
    __shared__ float tile[32][33];
    int b  = blockIdx.z;
    int s0 = blockIdx.x * 32;
    int c0 = blockIdx.y * 32;
    for (int i = threadIdx.y; i < 32; i += 8)
        tile[i][threadIdx.x] =
            points2[((size_t)b * C2 + (c0 + i)) * SS + s0 + threadIdx.x];
    __syncthreads();
    for (int i = threadIdx.y; i < 32; i += 8)
        g_p2t[((size_t)b * SS + (s0 + i)) * C2 + c0 + threadIdx.x] = tile[threadIdx.x][i];
}

// ---------------- points1 -> X0 rows [0,128) ----------------
__global__ void copy_p1(const float* __restrict__ points1) {
    const size_t total4 = (size_t)BB * C1 * NN / 4;   // 2,097,152 float4
    for (size_t i4 = (size_t)blockIdx.x * blockDim.x + threadIdx.x; i4 < total4;
         i4 += (size_t)gridDim.x * blockDim.x) {
        size_t i = i4 * 4;
        int n  = (int)(i & (NN - 1));
        int bc = (int)(i >> 13);
        int c  = bc & (C1 - 1);
        int b  = bc >> 7;
        float4 v = *(const float4*)(points1 + i);
        *(float4*)(g_X0 + (size_t)c * PP + (size_t)b * NN + n) = v;
    }
}

// ---------------- 3-NN interpolation -> X0 rows [128,384) ----------------
// one block = 32 points x 256 channels; SMEM transpose so both sides coalesce
__global__ __launch_bounds__(256) void interp_kernel() {
    __shared__ float tile[256][33];
    __shared__ int   sidx[32 * 3];
    __shared__ float swt [32 * 3];
    int p0 = blockIdx.x * 32;
    int b  = p0 >> 13;
    int t  = threadIdx.x;
    if (t < 96) { sidx[t] = g_idx[p0 * 3 + t]; swt[t] = g_wt[p0 * 3 + t]; }
    __syncthreads();
    const float* base = g_p2t + (size_t)b * SS * C2;
    #pragma unroll 4
    for (int pp = 0; pp < 32; pp++) {
        const float* r0 = base + (size_t)sidx[pp * 3 + 0] * C2;
        const float* r1 = base + (size_t)sidx[pp * 3 + 1] * C2;
        const float* r2 = base + (size_t)sidx[pp * 3 + 2] * C2;
        tile[t][pp] = swt[pp * 3 + 0] * r0[t] + swt[pp * 3 + 1] * r1[t]
                    + swt[pp * 3 + 2] * r2[t];
    }
    __syncthreads();
    #pragma unroll
    for (int j = 0; j < 32; j++) {
        int e  = t + 256 * j;
        int c  = e >> 5;
        int pp = e & 31;
        g_X0[(size_t)(C1 + c) * PP + p0 + pp] = tile[c][pp];
    }
}

// ---------------- SGEMM: C[M=256][P] = A[M][K] * B[K][P] + colbias[b][m] ----
// 128x128x16 tile, 8x8 per thread, 256 threads
__global__ __launch_bounds__(256) void sgemm_kernel(const float* __restrict__ A,
                                                    const float* __restrict__ B,
                                                    float* __restrict__ C,
                                                    const float* __restrict__ colbias,
                                                    int K) {
    __shared__ float As[16][128];
    __shared__ float Bs[16][128];
    int tid = threadIdx.x;
    int bm = blockIdx.y, bn = blockIdx.x;
    int aRow = tid >> 2;            // 0..63
    int aCol = (tid & 3) << 2;      // 0,4,8,12
    int bRow = tid >> 5;            // 0..7
    int bCol = (tid & 31) << 2;     // 0..124
    int tx = tid & 15, ty = tid >> 4;

    const float* Ab = A + (size_t)(bm * 128) * K;
    const float* Bb = B + (size_t)bn * 128;
    float acc[8][8];
    #pragma unroll
    for (int i = 0; i < 8; i++)
        #pragma unroll
        for (int j = 0; j < 8; j++) acc[i][j] = 0.0f;

    for (int k0 = 0; k0 < K; k0 += 16) {
        #pragma unroll
        for (int r = 0; r < 2; r++) {
            int m = aRow + r * 64;
            float4 v = *(const float4*)(Ab + (size_t)m * K + k0 + aCol);
            As[aCol + 0][m] = v.x; As[aCol + 1][m] = v.y;
            As[aCol + 2][m] = v.z; As[aCol + 3][m] = v.w;
        }
        #pragma unroll
        for (int r = 0; r < 2; r++) {
            int kk = bRow + r * 8;
            *(float4*)(&Bs[kk][bCol]) =
                *(const float4*)(Bb + (size_t)(k0 + kk) * PP + bCol);
        }
        __syncthreads();
        #pragma unroll
        for (int kk = 0; kk < 16; kk++) {
            float ra[8], rb[8];
            *(float4*)(ra)     = *(const float4*)(&As[kk][ty * 8]);
            *(float4*)(ra + 4) = *(const float4*)(&As[kk][ty * 8 + 4]);
            *(float4*)(rb)     = *(const float4*)(&Bs[kk][tx * 8]);
            *(float4*)(rb + 4) = *(const float4*)(&Bs[kk][tx * 8 + 4]);
            #pragma unroll
            for (int i = 0; i < 8; i++)
                #pragma unroll
                for (int j = 0; j < 8; j++)
                    acc[i][j] = fmaf(ra[i], rb[j], acc[i][j]);
        }
        __syncthreads();
    }
    int batch = (bn * 128) >> 13;   // 128-col tile never crosses a batch (8192%128==0)
    #pragma unroll
    for (int i = 0; i < 8; i++) {
        int m = bm * 128 + ty * 8 + i;
        float bias = colbias[batch * MM + m];
        float* Crow = C + (size_t)m * PP + bn * 128 + tx * 8;
        float4 v0 = make_float4(acc[i][0] + bias, acc[i][1] + bias,
                                acc[i][2] + bias, acc[i][3] + bias);
        float4 v1 = make_float4(acc[i][4] + bias, acc[i][5] + bias,
                                acc[i][6] + bias, acc[i][7] + bias);
        *(float4*)(Crow)     = v0;
        *(float4*)(Crow + 4) = v1;
    }
}

// ---------------- BatchNorm stats (biased, over all 65536 samples) ---------
__global__ __launch_bounds__(256) void bn_stats(const float* __restrict__ X,
                                                float* __restrict__ mean,
                                                float* __restrict__ var) {
    int o = blockIdx.x;
    const float* row = X + (size_t)o * PP;
    float s = 0.0f, s2 = 0.0f;
    for (int i = threadIdx.x; i < PP; i += 256) {
        float v = row[i];
        s += v;
        s2 = fmaf(v, v, s2);
    }
    __shared__ float sh[256], sh2[256];
    sh[threadIdx.x] = s; sh2[threadIdx.x] = s2;
    __syncthreads();
    for (int st = 128; st > 0; st >>= 1) {
        if (threadIdx.x < st) {
            sh [threadIdx.x] += sh [threadIdx.x + st];
            sh2[threadIdx.x] += sh2[threadIdx.x + st];
        }
        __syncthreads();
    }
    if (threadIdx.x == 0) {
        float m = sh[0] * (1.0f / PP);
        mean[o] = m;
        var[o]  = sh2[0] * (1.0f / PP) - m * m;
    }
}

// ---------------- BN + GELU, in place (layer 1) ----------------
__global__ void bn_act1(const float* __restrict__ gamma, const float* __restrict__ beta) {
    const size_t total4 = (size_t)MM * PP / 4;
    for (size_t i4 = (size_t)blockIdx.x * blockDim.x + threadIdx.x; i4 < total4;
         i4 += (size_t)gridDim.x * blockDim.x) {
        size_t i = i4 * 4;
        int o = (int)(i >> 16);
        float sc = gamma[o] * rsqrtf(g_v1[o] + 1e-5f);
        float sh = beta[o] - g_m1[o] * sc;
        float4 v = *(float4*)(g_Y + i);
        v.x = gelu_exact(fmaf(v.x, sc, sh));
        v.y = gelu_exact(fmaf(v.y, sc, sh));
        v.z = gelu_exact(fmaf(v.z, sc, sh));
        v.w = gelu_exact(fmaf(v.w, sc, sh));
        *(float4*)(g_Y + i) = v;
    }
}

// ---------------- BN + GELU + permute (o,p)->(b,o,n) into d_out ------------
__global__ void bn_act2_out(const float* __restrict__ gamma,
                            const float* __restrict__ beta,
                            float* __restrict__ out) {
    const size_t total4 = (size_t)MM * PP / 4;
    for (size_t i4 = (size_t)blockIdx.x * blockDim.x + threadIdx.x; i4 < total4;
         i4 += (size_t)gridDim.x * blockDim.x) {
        size_t i = i4 * 4;
        int o = (int)(i >> 16);
        int p = (int)(i & (PP - 1));
        int b = p >> 13;
        int n = p & (NN - 1);
        float sc = gamma[o] * rsqrtf(g_v2[o] + 1e-5f);
        float sh = beta[o] - g_m2[o] * sc;
        float4 v = *(float4*)(g_X0 + i);
        v.x = gelu_exact(fmaf(v.x, sc, sh));
        v.y = gelu_exact(fmaf(v.y, sc, sh));
        v.z = gelu_exact(fmaf(v.z, sc, sh));
        v.w = gelu_exact(fmaf(v.w, sc, sh));
        *(float4*)(out + ((size_t)(b * MM + o) << 13) + n) = v;
    }
}

// ---------------- launcher ----------------
extern "C" void kernel_launch(void* const* d_in, const int* in_sizes, int n_in,
                              void* d_out, int out_size) {
    const float* xyz1    = (const float*)d_in[0];
    const float* xyz2    = (const float*)d_in[1];
    const float* points1 = (const float*)d_in[2];
    const float* points2 = (const float*)d_in[3];
    const float* t_embed = (const float*)d_in[4];
    const float* w_t1 = (const float*)d_in[5];
    const float* b_t1 = (const float*)d_in[6];
    const float* w_c1 = (const float*)d_in[7];
    const float* b_c1 = (const float*)d_in[8];
    const float* g1   = (const float*)d_in[9];
    const float* be1  = (const float*)d_in[10];
    const float* w_t2 = (const float*)d_in[11];
    const float* b_t2 = (const float*)d_in[12];
    const float* w_c2 = (const float*)d_in[13];
    const float* b_c2 = (const float*)d_in[14];
    const float* g2   = (const float*)d_in[15];
    const float* be2  = (const float*)d_in[16];
    float* out = (float*)d_out;

    float* pX0; cudaGetSymbolAddress((void**)&pX0, g_X0);
    float* pY;  cudaGetSymbolAddress((void**)&pY,  g_Y);
    float* pm1; cudaGetSymbolAddress((void**)&pm1, g_m1);
    float* pv1; cudaGetSymbolAddress((void**)&pv1, g_v1);
    float* pm2; cudaGetSymbolAddress((void**)&pm2, g_m2);
    float* pv2; cudaGetSymbolAddress((void**)&pv2, g_v2);
    float* pb1; cudaGetSymbolAddress((void**)&pb1, g_bias1);
    float* pb2; cudaGetSymbolAddress((void**)&pb2, g_bias2);

    te_bias_kernel<<<BB, CIN>>>(t_embed, w_t1, b_t1, w_c1, b_c1,
                                w_t2, b_t2, w_c2, b_c2);
    knn_kernel<<<dim3(NN / 256, BB), 256>>>(xyz1, xyz2);
    transpose_p2<<<dim3(SS / 32, C2 / 32, BB), dim3(32, 8)>>>(points2);
    copy_p1<<<4096, 256>>>(points1);
    interp_kernel<<<PP / 32, 256>>>();

    sgemm_kernel<<<dim3(PP / 128, MM / 128), 256>>>(w_c1, pX0, pY, pb1, CIN);
    bn_stats<<<MM, 256>>>(pY, pm1, pv1);
    bn_act1<<<8192, 256>>>(g1, be1);

    sgemm_kernel<<<dim3(PP / 128, MM / 128), 256>>>(w_c2, pY, pX0, pb2, MM);
    bn_stats<<<MM, 256>>>(pX0, pm2, pv2);
    bn_act2_out<<<8192, 256>>>(g2, be2, out);
}

// round 3
// speedup vs baseline: 1.5979x; 1.5979x over previous
#include <cuda_runtime.h>
#include <cuda_fp16.h>
#include <math.h>
#include <stdint.h>

// ---------------- problem constants ----------------
#define BB   8
#define NN   8192
#define SS   2048
#define C1   128
#define C2   256
#define TT   256
#define CIN  384
#define PP   65536      // B*N
#define MM   256        // output channels of both convs

// ---------------- device scratch ----------------
__device__ __half g_X0h[(size_t)PP * CIN];   // conv1 input, point-major [p][384] fp16
__device__ __half g_X1h[(size_t)PP * MM];    // conv2 input, point-major [p][256] fp16
__device__ float  g_Y  [(size_t)PP * MM];    // preact (both layers), point-major [p][256] fp32
__device__ __half g_W1h[MM * CIN];
__device__ __half g_W2h[MM * MM];
__device__ float  g_p2t[(size_t)BB * SS * C2];  // points2 transposed (b,s,c) fp32
__device__ int    g_idx[PP * 3];
__device__ float  g_wt [PP * 3];
__device__ float  g_bias1[BB * MM];
__device__ float  g_bias2[BB * MM];
__device__ float  g_ps [256 * 256];
__device__ float  g_ps2[256 * 256];
__device__ float  g_sc[MM], g_sh[MM];        // BN scale/shift

__device__ __forceinline__ float gelu_exact(float x) {
    return 0.5f * x * (1.0f + erff(x * 0.70710678118654752440f));
}

__device__ __forceinline__ uint32_t smem_u32(const void* p) {
    return (uint32_t)__cvta_generic_to_shared(p);
}

#define CP_ASYNC16(dst, src) \
    asm volatile("cp.async.cg.shared.global [%0], [%1], 16;\n" :: "r"(dst), "l"(src))
#define CP_COMMIT() asm volatile("cp.async.commit_group;\n" ::: "memory")
#define CP_WAIT0()  asm volatile("cp.async.wait_group 0;\n" ::: "memory")

__device__ __forceinline__ void ldmatrix_x4(uint32_t& r0, uint32_t& r1,
                                            uint32_t& r2, uint32_t& r3, uint32_t addr) {
    asm volatile("ldmatrix.sync.aligned.m8n8.x4.shared.b16 {%0,%1,%2,%3}, [%4];"
                 : "=r"(r0), "=r"(r1), "=r"(r2), "=r"(r3) : "r"(addr));
}

__device__ __forceinline__ void mma16816(float* d, const uint32_t* a, const uint32_t* b) {
    asm volatile("mma.sync.aligned.m16n8k16.row.col.f32.f16.f16.f32 "
                 "{%0,%1,%2,%3}, {%4,%5,%6,%7}, {%8,%9}, {%0,%1,%2,%3};"
                 : "+f"(d[0]), "+f"(d[1]), "+f"(d[2]), "+f"(d[3])
                 : "r"(a[0]), "r"(a[1]), "r"(a[2]), "r"(a[3]), "r"(b[0]), "r"(b[1]));
}

// ---------------- time-conditioning biases ----------------
__global__ void te_bias_kernel(const float* __restrict__ t_embed,
                               const float* __restrict__ w_t1, const float* __restrict__ b_t1,
                               const float* __restrict__ w_c1, const float* __restrict__ b_c1,
                               const float* __restrict__ w_t2, const float* __restrict__ b_t2,
                               const float* __restrict__ w_c2, const float* __restrict__ b_c2) {
    __shared__ float ge[TT];
    __shared__ float te1[CIN];
    __shared__ float te2[MM];
    int b = blockIdx.x;
    int t = threadIdx.x;          // 0..383
    if (t < TT) ge[t] = gelu_exact(t_embed[b * TT + t]);
    __syncthreads();
    {
        float a = b_t1[t];
        const float* w = w_t1 + (size_t)t * TT;
        #pragma unroll 4
        for (int c = 0; c < TT; c++) a += ge[c] * w[c];
        te1[t] = a;
    }
    if (t < MM) {
        float a = b_t2[t];
        const float* w = w_t2 + (size_t)t * TT;
        #pragma unroll 4
        for (int c = 0; c < TT; c++) a += ge[c] * w[c];
        te2[t] = a;
    }
    __syncthreads();
    if (t < MM) {
        float a = b_c1[t];
        const float* w = w_c1 + (size_t)t * CIN;
        #pragma unroll 4
        for (int c = 0; c < CIN; c++) a += te1[c] * w[c];
        g_bias1[b * MM + t] = a;

        float a2 = b_c2[t];
        const float* w2 = w_c2 + (size_t)t * MM;
        #pragma unroll 4
        for (int c = 0; c < MM; c++) a2 += te2[c] * w2[c];
        g_bias2[b * MM + t] = a2;
    }
}

// ---------------- 3-NN (fused distance + top-3) ----------------
__global__ __launch_bounds__(256) void knn_kernel(const float* __restrict__ xyz1,
                                                  const float* __restrict__ xyz2) {
    __shared__ float4 sp[SS];
    int b = blockIdx.y;
    int n = blockIdx.x * 256 + threadIdx.x;
    const float* p2 = xyz2 + (size_t)b * SS * 3;
    for (int s = threadIdx.x; s < SS; s += 256) {
        float x = p2[s * 3 + 0], y = p2[s * 3 + 1], z = p2[s * 3 + 2];
        sp[s] = make_float4(x, y, z, x * x + y * y + z * z);
    }
    __syncthreads();
    const float* p1 = xyz1 + ((size_t)b * NN + n) * 3;
    float px = p1[0], py = p1[1], pz = p1[2];
    float n1 = px * px + py * py + pz * pz;

    float d0 = 1e30f, d1 = 1e30f, d2 = 1e30f;
    int   i0 = 0, i1 = 0, i2 = 0;
    for (int s = 0; s < SS; s++) {
        float4 q = sp[s];
        float t = fmaf(px, q.x, fmaf(py, q.y, pz * q.z));
        float d = n1 + q.w - 2.0f * t;
        if (d < d2) {
            if (d < d0)      { d2 = d1; i2 = i1; d1 = d0; i1 = i0; d0 = d; i0 = s; }
            else if (d < d1) { d2 = d1; i2 = i1; d1 = d; i1 = s; }
            else             { d2 = d; i2 = s; }
        }
    }
    float r0 = 1.0f / (d0 + 1e-8f);
    float r1 = 1.0f / (d1 + 1e-8f);
    float r2 = 1.0f / (d2 + 1e-8f);
    float inv = 1.0f / (r0 + r1 + r2);
    int base = (b * NN + n) * 3;
    g_idx[base + 0] = i0; g_idx[base + 1] = i1; g_idx[base + 2] = i2;
    g_wt [base + 0] = r0 * inv; g_wt [base + 1] = r1 * inv; g_wt [base + 2] = r2 * inv;
}

// ---------------- transpose points2 (B,C2,S) -> (B,S,C2) fp32 ----------------
__global__ void transpose_p2(const float* __restrict__ points2) {
    __shared__ float tile[32][33];
    int b  = blockIdx.z;
    int s0 = blockIdx.x * 32;
    int c0 = blockIdx.y * 32;
    for (int i = threadIdx.y; i < 32; i += 8)
        tile[i][threadIdx.x] =
            points2[((size_t)b * C2 + (c0 + i)) * SS + s0 + threadIdx.x];
    __syncthreads();
    for (int i = threadIdx.y; i < 32; i += 8)
        g_p2t[((size_t)b * SS + (s0 + i)) * C2 + c0 + threadIdx.x] = tile[threadIdx.x][i];
}

// ---------------- weight fp32 -> fp16 ----------------
__global__ void convw_kernel(const float* __restrict__ w, __half* __restrict__ out, int n) {
    int i = blockIdx.x * 256 + threadIdx.x;
    if (i < n) out[i] = __float2half_rn(w[i]);
}

// ---------------- points1 (b,c,n) -> X0h[p][c], c in [0,128), fp16 ----------
__global__ void tr_p1_kernel(const float* __restrict__ points1) {
    __shared__ float tile[32][33];
    int b  = blockIdx.z;
    int n0 = blockIdx.x * 32;
    int c0 = blockIdx.y * 32;
    int tx = threadIdx.x, ty = threadIdx.y;
    for (int i = ty; i < 32; i += 8)
        tile[i][tx] = points1[((size_t)(b * C1 + c0 + i) << 13) + n0 + tx];
    __syncthreads();
    for (int i = ty; i < 32; i += 8)
        g_X0h[(size_t)(b * NN + n0 + i) * CIN + c0 + tx] = __float2half_rn(tile[tx][i]);
}

// ---------------- 3-NN interpolation -> X0h[p][128..384), fp16 -------------
__global__ __launch_bounds__(256) void interp_kernel() {
    __shared__ int   sidx[32 * 3];
    __shared__ float swt [32 * 3];
    int p0 = blockIdx.x * 32;
    int b  = p0 >> 13;
    int t  = threadIdx.x;   // channel 0..255
    if (t < 96) { sidx[t] = g_idx[p0 * 3 + t]; swt[t] = g_wt[p0 * 3 + t]; }
    __syncthreads();
    const float* base = g_p2t + (size_t)b * SS * C2;
    #pragma unroll 4
    for (int pp = 0; pp < 32; pp++) {
        const float* r0 = base + (size_t)sidx[pp * 3 + 0] * C2;
        const float* r1 = base + (size_t)sidx[pp * 3 + 1] * C2;
        const float* r2 = base + (size_t)sidx[pp * 3 + 2] * C2;
        float v = swt[pp * 3 + 0] * r0[t] + swt[pp * 3 + 1] * r1[t]
                + swt[pp * 3 + 2] * r2[t];
        g_X0h[(size_t)(p0 + pp) * CIN + C1 + t] = __float2half_rn(v);
    }
}

// ---------------- HMMA GEMM: Y[p][o] = sum_k Xh[p][k]*Wh[o][k] + bias[b][o]
// CTA: 128 points x 128 channels, BK=32, 8 warps (2x4), warp tile 64x32.
// SMEM XOR swizzle: 64B rows of 4x16B chunks, chunk ^= (row & 3).
template<int K>
__global__ __launch_bounds__(256) void gemm_hmma_kernel(
    const __half* __restrict__ Xh,      // [P][K]
    const __half* __restrict__ Wh,      // [256][K]
    const float* __restrict__ colbias,  // [B][256]
    float* __restrict__ Y)              // [P][256]
{
    __shared__ __half As[2][128 * 32];
    __shared__ __half Bs[2][128 * 32];
    __shared__ float sbias[128];

    const int tid = threadIdx.x;
    const int lane = tid & 31;
    const int wid = tid >> 5;
    const int warp_m = wid >> 2;   // 0..1
    const int warp_n = wid & 3;    // 0..3
    const int p0 = blockIdx.x * 128;
    const int o0 = blockIdx.y * 128;

    if (tid < 128) sbias[tid] = colbias[(p0 >> 13) * MM + o0 + tid];

    const uint32_t sA0 = smem_u32(As[0]), sA1 = smem_u32(As[1]);
    const uint32_t sB0 = smem_u32(Bs[0]), sB1 = smem_u32(Bs[1]);

    // cp.async loader: 512 16B-chunks per operand per stage, 2 per thread
    auto load_stage = [&](uint32_t sa, uint32_t sb, int k0) {
        #pragma unroll
        for (int i = 0; i < 2; i++) {
            int idx = tid + i * 256;
            int row = idx >> 2, ch = idx & 3;
            uint32_t doff = ((uint32_t)(row * 32 + ((ch ^ (row & 3)) * 8))) * 2;
            CP_ASYNC16(sa + doff, Xh + (size_t)(p0 + row) * K + k0 + ch * 8);
            CP_ASYNC16(sb + doff, Wh + (size_t)(o0 + row) * K + k0 + ch * 8);
        }
        CP_COMMIT();
    };

    float acc[4][4][4];
    #pragma unroll
    for (int mt = 0; mt < 4; mt++)
        #pragma unroll
        for (int nt = 0; nt < 4; nt++)
            #pragma unroll
            for (int e = 0; e < 4; e++) acc[mt][nt][e] = 0.0f;

    // per-lane ldmatrix address components
    const int a_row_off = (lane & 7) + ((lane >> 3) & 1) * 8;  // + warp_m*64 + mt*16
    const int a_ch_off  = lane >> 4;                           // + ks*2
    const int b_mat     = lane >> 3;
    const int b_row_off = ((b_mat >> 1) * 8) + (lane & 7);     // + warp_n*32 + nt2*16
    const int b_ch_off  = b_mat & 1;                           // + ks*2

    constexpr int NT = K / 32;
    load_stage(sA0, sB0, 0);

    #pragma unroll 2
    for (int t = 0; t < NT; t++) {
        const uint32_t sa = (t & 1) ? sA1 : sA0;
        const uint32_t sb = (t & 1) ? sB1 : sB0;
        CP_WAIT0();
        __syncthreads();
        if (t + 1 < NT)
            load_stage((t & 1) ? sA0 : sA1, (t & 1) ? sB0 : sB1, (t + 1) * 32);

        #pragma unroll
        for (int ks = 0; ks < 2; ks++) {
            uint32_t a[4][4];
            #pragma unroll
            for (int mt = 0; mt < 4; mt++) {
                int row = warp_m * 64 + mt * 16 + a_row_off;
                int ch  = ks * 2 + a_ch_off;
                uint32_t addr = sa + ((uint32_t)(row * 32 + ((ch ^ (row & 3)) * 8))) * 2;
                ldmatrix_x4(a[mt][0], a[mt][1], a[mt][2], a[mt][3], addr);
            }
            uint32_t b[4][2];
            #pragma unroll
            for (int nt2 = 0; nt2 < 2; nt2++) {
                int row = warp_n * 32 + nt2 * 16 + b_row_off;
                int ch  = ks * 2 + b_ch_off;
                uint32_t addr = sb + ((uint32_t)(row * 32 + ((ch ^ (row & 3)) * 8))) * 2;
                ldmatrix_x4(b[nt2 * 2][0], b[nt2 * 2][1],
                            b[nt2 * 2 + 1][0], b[nt2 * 2 + 1][1], addr);
            }
            #pragma unroll
            for (int mt = 0; mt < 4; mt++)
                #pragma unroll
                for (int nt = 0; nt < 4; nt++)
                    mma16816(acc[mt][nt], a[mt], b[nt]);
        }
        __syncthreads();
    }

    // epilogue: add bias, store fp32 point-major
    const int r_base = p0 + warp_m * 64 + (lane >> 2);
    #pragma unroll
    for (int mt = 0; mt < 4; mt++) {
        #pragma unroll
        for (int nt = 0; nt < 4; nt++) {
            int col = warp_n * 32 + nt * 8 + 2 * (lane & 3);
            float b0 = sbias[col], b1 = sbias[col + 1];
            int r0 = r_base + mt * 16;
            float2 v0 = make_float2(acc[mt][nt][0] + b0, acc[mt][nt][1] + b1);
            float2 v1 = make_float2(acc[mt][nt][2] + b0, acc[mt][nt][3] + b1);
            *(float2*)(Y + (size_t)r0 * MM + o0 + col)       = v0;
            *(float2*)(Y + (size_t)(r0 + 8) * MM + o0 + col) = v1;
        }
    }
}

// ---------------- BN partial sums (point-major, coalesced) ----------------
__global__ __launch_bounds__(256) void bn_part_kernel(const float* __restrict__ Y) {
    int o = threadIdx.x;
    int j = blockIdx.x;                 // 256 blocks x 256 points each
    const float* base = Y + (size_t)j * 256 * MM + o;
    float s = 0.0f, s2 = 0.0f;
    #pragma unroll 4
    for (int i = 0; i < 256; i++) {
        float v = base[(size_t)i * MM];
        s += v;
        s2 = fmaf(v, v, s2);
    }
    g_ps [j * 256 + o] = s;
    g_ps2[j * 256 + o] = s2;
}

__global__ void bn_finish_kernel(const float* __restrict__ gamma,
                                 const float* __restrict__ beta) {
    int o = threadIdx.x;
    float s = 0.0f, s2 = 0.0f;
    for (int j = 0; j < 256; j++) { s += g_ps[j * 256 + o]; s2 += g_ps2[j * 256 + o]; }
    float m = s * (1.0f / PP);
    float v = s2 * (1.0f / PP) - m * m;
    float sc = gamma[o] * rsqrtf(v + 1e-5f);
    g_sc[o] = sc;
    g_sh[o] = beta[o] - m * sc;
}

// ---------------- BN + GELU -> fp16 point-major (layer 1) ----------------
__global__ __launch_bounds__(256) void bn_act_h_kernel(const float* __restrict__ Y,
                                                       __half* __restrict__ Xh) {
    __shared__ float ssc[MM], ssh[MM];
    if (threadIdx.x < MM) { ssc[threadIdx.x] = g_sc[threadIdx.x]; ssh[threadIdx.x] = g_sh[threadIdx.x]; }
    __syncthreads();
    size_t i4 = (size_t)blockIdx.x * 256 + threadIdx.x;   // 16384 blocks
    size_t i = i4 * 4;
    int o = (int)(i & (MM - 1));
    float4 v = *(const float4*)(Y + i);
    float a0 = gelu_exact(fmaf(v.x, ssc[o + 0], ssh[o + 0]));
    float a1 = gelu_exact(fmaf(v.y, ssc[o + 1], ssh[o + 1]));
    float a2 = gelu_exact(fmaf(v.z, ssc[o + 2], ssh[o + 2]));
    float a3 = gelu_exact(fmaf(v.w, ssc[o + 3], ssh[o + 3]));
    __half2* dst = (__half2*)(Xh + i);
    dst[0] = __floats2half2_rn(a0, a1);
    dst[1] = __floats2half2_rn(a2, a3);
}

// ---------------- BN + GELU + transpose (p,o) -> out (b,o,n) --------------
__global__ void bn_out_kernel(const float* __restrict__ Y2, float* __restrict__ out) {
    __shared__ float tile[32][33];
    int p0 = blockIdx.x * 32;
    int o0 = blockIdx.y * 32;
    int tx = threadIdx.x, ty = threadIdx.y;
    for (int i = ty; i < 32; i += 8) {
        int o = o0 + tx;
        float v = Y2[(size_t)(p0 + i) * MM + o];
        tile[i][tx] = gelu_exact(fmaf(v, g_sc[o], g_sh[o]));
    }
    __syncthreads();
    int b  = p0 >> 13;
    int n0 = p0 & (NN - 1);
    for (int i = ty; i < 32; i += 8)
        out[((size_t)(b * MM + o0 + i) << 13) + n0 + tx] = tile[tx][i];
}

// ---------------- launcher ----------------
extern "C" void kernel_launch(void* const* d_in, const int* in_sizes, int n_in,
                              void* d_out, int out_size) {
    const float* xyz1    = (const float*)d_in[0];
    const float* xyz2    = (const float*)d_in[1];
    const float* points1 = (const float*)d_in[2];
    const float* points2 = (const float*)d_in[3];
    const float* t_embed = (const float*)d_in[4];
    const float* w_t1 = (const float*)d_in[5];
    const float* b_t1 = (const float*)d_in[6];
    const float* w_c1 = (const float*)d_in[7];
    const float* b_c1 = (const float*)d_in[8];
    const float* g1   = (const float*)d_in[9];
    const float* be1  = (const float*)d_in[10];
    const float* w_t2 = (const float*)d_in[11];
    const float* b_t2 = (const float*)d_in[12];
    const float* w_c2 = (const float*)d_in[13];
    const float* b_c2 = (const float*)d_in[14];
    const float* g2   = (const float*)d_in[15];
    const float* be2  = (const float*)d_in[16];
    float* out = (float*)d_out;

    __half* pX0h; cudaGetSymbolAddress((void**)&pX0h, g_X0h);
    __half* pX1h; cudaGetSymbolAddress((void**)&pX1h, g_X1h);
    float*  pY;   cudaGetSymbolAddress((void**)&pY,   g_Y);
    __half* pW1h; cudaGetSymbolAddress((void**)&pW1h, g_W1h);
    __half* pW2h; cudaGetSymbolAddress((void**)&pW2h, g_W2h);
    float*  pb1;  cudaGetSymbolAddress((void**)&pb1,  g_bias1);
    float*  pb2;  cudaGetSymbolAddress((void**)&pb2,  g_bias2);

    // ---- prep ----
    te_bias_kernel<<<BB, CIN>>>(t_embed, w_t1, b_t1, w_c1, b_c1, w_t2, b_t2, w_c2, b_c2);
    knn_kernel<<<dim3(NN / 256, BB), 256>>>(xyz1, xyz2);
    transpose_p2<<<dim3(SS / 32, C2 / 32, BB), dim3(32, 8)>>>(points2);
    convw_kernel<<<(MM * CIN + 255) / 256, 256>>>(w_c1, pW1h, MM * CIN);
    convw_kernel<<<(MM * MM + 255) / 256, 256>>>(w_c2, pW2h, MM * MM);
    tr_p1_kernel<<<dim3(NN / 32, C1 / 32, BB), dim3(32, 8)>>>(points1);
    interp_kernel<<<PP / 32, 256>>>();

    // ---- layer 1 ----
    gemm_hmma_kernel<CIN><<<dim3(PP / 128, MM / 128), 256>>>(pX0h, pW1h, pb1, pY);
    bn_part_kernel<<<256, 256>>>(pY);
    bn_finish_kernel<<<1, 256>>>(g1, be1);
    bn_act_h_kernel<<<PP * MM / 1024, 256>>>(pY, pX1h);

    // ---- layer 2 ----
    gemm_hmma_kernel<MM><<<dim3(PP / 128, MM / 128), 256>>>(pX1h, pW2h, pb2, pY);
    bn_part_kernel<<<256, 256>>>(pY);
    bn_finish_kernel<<<1, 256>>>(g2, be2);
    bn_out_kernel<<<dim3(PP / 32, MM / 32), dim3(32, 8)>>>(pY, out);
}

// round 4
// speedup vs baseline: 1.7298x; 1.0825x over previous
#include <cuda_runtime.h>
#include <cuda_fp16.h>
#include <math.h>
#include <stdint.h>

// ---------------- problem constants ----------------
#define BB   8
#define NN   8192
#define SS   2048
#define C1   128
#define C2   256
#define TT   256
#define CIN  384
#define PP   65536      // B*N
#define MM   256        // output channels of both convs

// ---------------- device scratch ----------------
__device__ __half g_X0h[(size_t)PP * CIN];   // conv1 input, point-major [p][384] fp16
__device__ __half g_X1h[(size_t)PP * MM];    // conv2 input, point-major [p][256] fp16
__device__ float  g_Y  [(size_t)PP * MM];    // preact (both layers), point-major fp32
__device__ __half g_W1h[MM * CIN];
__device__ __half g_W2h[MM * MM];
__device__ float  g_p2t[(size_t)BB * SS * C2];  // points2 transposed (b,s,c) fp32
__device__ int    g_idx[PP * 3];
__device__ float  g_wt [PP * 3];
__device__ float  g_bias1[BB * MM];
__device__ float  g_bias2[BB * MM];
__device__ float  g_s1[MM], g_s2[MM];        // BN accumulators (atomic)
__device__ float  g_sc[MM], g_sh[MM];        // BN scale/shift

__device__ __forceinline__ float gelu_exact(float x) {
    return 0.5f * x * (1.0f + erff(x * 0.70710678118654752440f));
}

__device__ __forceinline__ uint32_t smem_u32(const void* p) {
    return (uint32_t)__cvta_generic_to_shared(p);
}

#define CP_ASYNC16(dst, src) \
    asm volatile("cp.async.cg.shared.global [%0], [%1], 16;\n" :: "r"(dst), "l"(src))
#define CP_COMMIT() asm volatile("cp.async.commit_group;\n" ::: "memory")
#define CP_WAIT2()  asm volatile("cp.async.wait_group 2;\n" ::: "memory")

__device__ __forceinline__ void ldmatrix_x4(uint32_t& r0, uint32_t& r1,
                                            uint32_t& r2, uint32_t& r3, uint32_t addr) {
    asm volatile("ldmatrix.sync.aligned.m8n8.x4.shared.b16 {%0,%1,%2,%3}, [%4];"
                 : "=r"(r0), "=r"(r1), "=r"(r2), "=r"(r3) : "r"(addr));
}

__device__ __forceinline__ void mma16816(float* d, const uint32_t* a, const uint32_t* b) {
    asm volatile("mma.sync.aligned.m16n8k16.row.col.f32.f16.f16.f32 "
                 "{%0,%1,%2,%3}, {%4,%5,%6,%7}, {%8,%9}, {%0,%1,%2,%3};"
                 : "+f"(d[0]), "+f"(d[1]), "+f"(d[2]), "+f"(d[3])
                 : "r"(a[0]), "r"(a[1]), "r"(a[2]), "r"(a[3]), "r"(b[0]), "r"(b[1]));
}

// ---------------- time-conditioning biases ----------------
__global__ void te_bias_kernel(const float* __restrict__ t_embed,
                               const float* __restrict__ w_t1, const float* __restrict__ b_t1,
                               const float* __restrict__ w_c1, const float* __restrict__ b_c1,
                               const float* __restrict__ w_t2, const float* __restrict__ b_t2,
                               const float* __restrict__ w_c2, const float* __restrict__ b_c2) {
    __shared__ float ge[TT];
    __shared__ float te1[CIN];
    __shared__ float te2[MM];
    int b = blockIdx.x;
    int t = threadIdx.x;          // 0..383
    if (t < TT) ge[t] = gelu_exact(t_embed[b * TT + t]);
    __syncthreads();
    {
        float a = b_t1[t];
        const float* w = w_t1 + (size_t)t * TT;
        #pragma unroll 4
        for (int c = 0; c < TT; c++) a += ge[c] * w[c];
        te1[t] = a;
    }
    if (t < MM) {
        float a = b_t2[t];
        const float* w = w_t2 + (size_t)t * TT;
        #pragma unroll 4
        for (int c = 0; c < TT; c++) a += ge[c] * w[c];
        te2[t] = a;
    }
    __syncthreads();
    if (t < MM) {
        float a = b_c1[t];
        const float* w = w_c1 + (size_t)t * CIN;
        #pragma unroll 4
        for (int c = 0; c < CIN; c++) a += te1[c] * w[c];
        g_bias1[b * MM + t] = a;

        float a2 = b_c2[t];
        const float* w2 = w_c2 + (size_t)t * MM;
        #pragma unroll 4
        for (int c = 0; c < MM; c++) a2 += te2[c] * w2[c];
        g_bias2[b * MM + t] = a2;
    }
}

// ---------------- 3-NN (fused distance + top-3) ----------------
__global__ __launch_bounds__(256) void knn_kernel(const float* __restrict__ xyz1,
                                                  const float* __restrict__ xyz2) {
    __shared__ float4 sp[SS];
    int b = blockIdx.y;
    int n = blockIdx.x * 256 + threadIdx.x;
    const float* p2 = xyz2 + (size_t)b * SS * 3;
    for (int s = threadIdx.x; s < SS; s += 256) {
        float x = p2[s * 3 + 0], y = p2[s * 3 + 1], z = p2[s * 3 + 2];
        sp[s] = make_float4(x, y, z, x * x + y * y + z * z);
    }
    __syncthreads();
    const float* p1 = xyz1 + ((size_t)b * NN + n) * 3;
    float px = p1[0], py = p1[1], pz = p1[2];
    float n1 = px * px + py * py + pz * pz;

    float d0 = 1e30f, d1 = 1e30f, d2 = 1e30f;
    int   i0 = 0, i1 = 0, i2 = 0;
    for (int s = 0; s < SS; s++) {
        float4 q = sp[s];
        float t = fmaf(px, q.x, fmaf(py, q.y, pz * q.z));
        float d = n1 + q.w - 2.0f * t;
        if (d < d2) {
            if (d < d0)      { d2 = d1; i2 = i1; d1 = d0; i1 = i0; d0 = d; i0 = s; }
            else if (d < d1) { d2 = d1; i2 = i1; d1 = d; i1 = s; }
            else             { d2 = d; i2 = s; }
        }
    }
    float r0 = 1.0f / (d0 + 1e-8f);
    float r1 = 1.0f / (d1 + 1e-8f);
    float r2 = 1.0f / (d2 + 1e-8f);
    float inv = 1.0f / (r0 + r1 + r2);
    int base = (b * NN + n) * 3;
    g_idx[base + 0] = i0; g_idx[base + 1] = i1; g_idx[base + 2] = i2;
    g_wt [base + 0] = r0 * inv; g_wt [base + 1] = r1 * inv; g_wt [base + 2] = r2 * inv;
}

// ---------------- transpose points2 (B,C2,S) -> (B,S,C2) fp32 ----------------
__global__ void transpose_p2(const float* __restrict__ points2) {
    __shared__ float tile[32][33];
    int b  = blockIdx.z;
    int s0 = blockIdx.x * 32;
    int c0 = blockIdx.y * 32;
    for (int i = threadIdx.y; i < 32; i += 8)
        tile[i][threadIdx.x] =
            points2[((size_t)b * C2 + (c0 + i)) * SS + s0 + threadIdx.x];
    __syncthreads();
    for (int i = threadIdx.y; i < 32; i += 8)
        g_p2t[((size_t)b * SS + (s0 + i)) * C2 + c0 + threadIdx.x] = tile[threadIdx.x][i];
}

// ---------------- weights fp32 -> fp16 (both layers, one launch) -----------
__global__ void convw_kernel(const float* __restrict__ w1, const float* __restrict__ w2) {
    int i = blockIdx.x * 256 + threadIdx.x;
    if (i < MM * CIN) g_W1h[i] = __float2half_rn(w1[i]);
    else {
        int j = i - MM * CIN;
        if (j < MM * MM) g_W2h[j] = __float2half_rn(w2[j]);
    }
}

// ---------------- points1 (b,c,n) -> X0h[p][c], c in [0,128), fp16 ----------
__global__ void tr_p1_kernel(const float* __restrict__ points1) {
    __shared__ float tile[32][33];
    int b  = blockIdx.z;
    int n0 = blockIdx.x * 32;
    int c0 = blockIdx.y * 32;
    int tx = threadIdx.x, ty = threadIdx.y;
    for (int i = ty; i < 32; i += 8)
        tile[i][tx] = points1[((size_t)(b * C1 + c0 + i) << 13) + n0 + tx];
    __syncthreads();
    for (int i = ty; i < 32; i += 8)
        g_X0h[(size_t)(b * NN + n0 + i) * CIN + c0 + tx] = __float2half_rn(tile[tx][i]);
}

// ---------------- 3-NN interpolation -> X0h[p][128..384), fp16 -------------
__global__ __launch_bounds__(256) void interp_kernel() {
    __shared__ int   sidx[32 * 3];
    __shared__ float swt [32 * 3];
    int p0 = blockIdx.x * 32;
    int b  = p0 >> 13;
    int t  = threadIdx.x;   // channel 0..255
    if (t < 96) { sidx[t] = g_idx[p0 * 3 + t]; swt[t] = g_wt[p0 * 3 + t]; }
    __syncthreads();
    const float* base = g_p2t + (size_t)b * SS * C2;
    #pragma unroll 4
    for (int pp = 0; pp < 32; pp++) {
        const float* r0 = base + (size_t)sidx[pp * 3 + 0] * C2;
        const float* r1 = base + (size_t)sidx[pp * 3 + 1] * C2;
        const float* r2 = base + (size_t)sidx[pp * 3 + 2] * C2;
        float v = swt[pp * 3 + 0] * r0[t] + swt[pp * 3 + 1] * r1[t]
                + swt[pp * 3 + 2] * r2[t];
        g_X0h[(size_t)(p0 + pp) * CIN + C1 + t] = __float2half_rn(v);
    }
}

// ---------------- HMMA GEMM: Y[p][o] = sum_k Xh[p][k]*Wh[o][k] + bias[b][o]
// CTA: 128 points x 256 channels (ALL), BK=32, 4-stage cp.async pipeline,
// 8 warps (2x4), warp tile 64x64. Fused BN partial-stat accumulation.
// SMEM XOR swizzle: 64B rows of 4x16B chunks, chunk ^= (row & 3).
#define STAGE_B 24576      // bytes per stage: A 8192 + B 16384
template<int K>
__global__ __launch_bounds__(256, 1) void gemm_hmma_kernel(
    const __half* __restrict__ Xh,      // [P][K]
    const __half* __restrict__ Wh,      // [256][K]
    const float* __restrict__ colbias,  // [B][256]
    float* __restrict__ Y)              // [P][256]
{
    extern __shared__ __align__(16) char smem[];
    const uint32_t sbase = smem_u32(smem);
    float* sbias = (float*)(smem + 4 * STAGE_B);

    const int tid = threadIdx.x;
    const int lane = tid & 31;
    const int wid = tid >> 5;
    const int warp_m = wid >> 2;   // 0..1
    const int warp_n = wid & 3;    // 0..3
    const int p0 = blockIdx.x * 128;

    sbias[tid] = colbias[(p0 >> 13) * MM + tid];

    // chunk loader: A 512 + B 1024 16B-chunks per stage
    auto load_stage = [&](int t) {
        const uint32_t base = sbase + (uint32_t)(t & 3) * STAGE_B;
        const int k0 = t * 32;
        #pragma unroll
        for (int i = 0; i < 2; i++) {
            int idx = tid + i * 256;
            int row = idx >> 2, ch = idx & 3;
            uint32_t doff = ((uint32_t)(row * 32 + ((ch ^ (row & 3)) * 8))) * 2;
            CP_ASYNC16(base + doff, Xh + (size_t)(p0 + row) * K + k0 + ch * 8);
        }
        #pragma unroll
        for (int i = 0; i < 4; i++) {
            int idx = tid + i * 256;
            int row = idx >> 2, ch = idx & 3;
            uint32_t doff = 8192u + ((uint32_t)(row * 32 + ((ch ^ (row & 3)) * 8))) * 2;
            CP_ASYNC16(base + doff, Wh + (size_t)row * K + k0 + ch * 8);
        }
        CP_COMMIT();
    };

    float acc[4][8][4];
    #pragma unroll
    for (int mt = 0; mt < 4; mt++)
        #pragma unroll
        for (int nt = 0; nt < 8; nt++)
            #pragma unroll
            for (int e = 0; e < 4; e++) acc[mt][nt][e] = 0.0f;

    const int a_row_off = (lane & 7) + ((lane >> 3) & 1) * 8;
    const int a_ch_off  = lane >> 4;
    const int b_mat     = lane >> 3;
    const int b_row_off = ((b_mat >> 1) * 8) + (lane & 7);
    const int b_ch_off  = b_mat & 1;

    constexpr int NT = K / 32;
    load_stage(0); load_stage(1); load_stage(2);
    CP_WAIT2();
    __syncthreads();

    for (int t = 0; t < NT; t++) {
        const uint32_t sA = sbase + (uint32_t)(t & 3) * STAGE_B;
        const uint32_t sB = sA + 8192u;
        #pragma unroll
        for (int ks = 0; ks < 2; ks++) {
            uint32_t a[4][4];
            #pragma unroll
            for (int mt = 0; mt < 4; mt++) {
                int row = warp_m * 64 + mt * 16 + a_row_off;
                int ch  = ks * 2 + a_ch_off;
                uint32_t addr = sA + ((uint32_t)(row * 32 + ((ch ^ (row & 3)) * 8))) * 2;
                ldmatrix_x4(a[mt][0], a[mt][1], a[mt][2], a[mt][3], addr);
            }
            uint32_t b[8][2];
            #pragma unroll
            for (int nt2 = 0; nt2 < 4; nt2++) {
                int row = warp_n * 64 + nt2 * 16 + b_row_off;
                int ch  = ks * 2 + b_ch_off;
                uint32_t addr = sB + ((uint32_t)(row * 32 + ((ch ^ (row & 3)) * 8))) * 2;
                ldmatrix_x4(b[nt2 * 2][0], b[nt2 * 2][1],
                            b[nt2 * 2 + 1][0], b[nt2 * 2 + 1][1], addr);
            }
            #pragma unroll
            for (int mt = 0; mt < 4; mt++)
                #pragma unroll
                for (int nt = 0; nt < 8; nt++)
                    mma16816(acc[mt][nt], a[mt], b[nt]);
        }
        if (t + 3 < NT) load_stage(t + 3); else CP_COMMIT();
        CP_WAIT2();
        __syncthreads();
    }

    // epilogue: bias add, store Y, fused BN partial sums
    float ps[16], ps2v[16];
    #pragma unroll
    for (int j = 0; j < 16; j++) { ps[j] = 0.0f; ps2v[j] = 0.0f; }

    const int r_base = p0 + warp_m * 64 + (lane >> 2);
    #pragma unroll
    for (int nt = 0; nt < 8; nt++) {
        int col = warp_n * 64 + nt * 8 + 2 * (lane & 3);
        float b0 = sbias[col], b1 = sbias[col + 1];
        #pragma unroll
        for (int mt = 0; mt < 4; mt++) {
            int r0 = r_base + mt * 16;
            float v00 = acc[mt][nt][0] + b0, v01 = acc[mt][nt][1] + b1;
            float v10 = acc[mt][nt][2] + b0, v11 = acc[mt][nt][3] + b1;
            *(float2*)(Y + (size_t)r0 * MM + col)       = make_float2(v00, v01);
            *(float2*)(Y + (size_t)(r0 + 8) * MM + col) = make_float2(v10, v11);
            ps  [nt * 2]     += v00 + v10;
            ps  [nt * 2 + 1] += v01 + v11;
            ps2v[nt * 2]     += v00 * v00 + v10 * v10;
            ps2v[nt * 2 + 1] += v01 * v01 + v11 * v11;
        }
    }
    #pragma unroll
    for (int off = 4; off < 32; off <<= 1) {
        #pragma unroll
        for (int j = 0; j < 16; j++) {
            ps[j]   += __shfl_xor_sync(0xffffffffu, ps[j],   off);
            ps2v[j] += __shfl_xor_sync(0xffffffffu, ps2v[j], off);
        }
    }
    if (lane < 4) {
        #pragma unroll
        for (int nt = 0; nt < 8; nt++) {
            int col = warp_n * 64 + nt * 8 + 2 * lane;
            atomicAdd(&g_s1[col],     ps[nt * 2]);
            atomicAdd(&g_s1[col + 1], ps[nt * 2 + 1]);
            atomicAdd(&g_s2[col],     ps2v[nt * 2]);
            atomicAdd(&g_s2[col + 1], ps2v[nt * 2 + 1]);
        }
    }
}

__global__ void bn_finish_kernel(const float* __restrict__ gamma,
                                 const float* __restrict__ beta) {
    int o = threadIdx.x;
    float m = g_s1[o] * (1.0f / PP);
    float v = g_s2[o] * (1.0f / PP) - m * m;
    float sc = gamma[o] * rsqrtf(v + 1e-5f);
    g_sc[o] = sc;
    g_sh[o] = beta[o] - m * sc;
}

// ---------------- BN + GELU -> fp16 point-major (layer 1) ----------------
__global__ __launch_bounds__(256) void bn_act_h_kernel(const float* __restrict__ Y,
                                                       __half* __restrict__ Xh) {
    __shared__ float ssc[MM], ssh[MM];
    if (threadIdx.x < MM) { ssc[threadIdx.x] = g_sc[threadIdx.x]; ssh[threadIdx.x] = g_sh[threadIdx.x]; }
    __syncthreads();
    size_t i4 = (size_t)blockIdx.x * 256 + threadIdx.x;
    size_t i = i4 * 4;
    int o = (int)(i & (MM - 1));
    float4 v = *(const float4*)(Y + i);
    float a0 = gelu_exact(fmaf(v.x, ssc[o + 0], ssh[o + 0]));
    float a1 = gelu_exact(fmaf(v.y, ssc[o + 1], ssh[o + 1]));
    float a2 = gelu_exact(fmaf(v.z, ssc[o + 2], ssh[o + 2]));
    float a3 = gelu_exact(fmaf(v.w, ssc[o + 3], ssh[o + 3]));
    __half2* dst = (__half2*)(Xh + i);
    dst[0] = __floats2half2_rn(a0, a1);
    dst[1] = __floats2half2_rn(a2, a3);
}

// ---------------- BN + GELU + transpose (p,o) -> out (b,o,n) --------------
__global__ void bn_out_kernel(const float* __restrict__ Y2, float* __restrict__ out) {
    __shared__ float tile[32][33];
    int p0 = blockIdx.x * 32;
    int o0 = blockIdx.y * 32;
    int tx = threadIdx.x, ty = threadIdx.y;
    for (int i = ty; i < 32; i += 8) {
        int o = o0 + tx;
        float v = Y2[(size_t)(p0 + i) * MM + o];
        tile[i][tx] = gelu_exact(fmaf(v, g_sc[o], g_sh[o]));
    }
    __syncthreads();
    int b  = p0 >> 13;
    int n0 = p0 & (NN - 1);
    for (int i = ty; i < 32; i += 8)
        out[((size_t)(b * MM + o0 + i) << 13) + n0 + tx] = tile[tx][i];
}

// ---------------- launcher ----------------
extern "C" void kernel_launch(void* const* d_in, const int* in_sizes, int n_in,
                              void* d_out, int out_size) {
    const float* xyz1    = (const float*)d_in[0];
    const float* xyz2    = (const float*)d_in[1];
    const float* points1 = (const float*)d_in[2];
    const float* points2 = (const float*)d_in[3];
    const float* t_embed = (const float*)d_in[4];
    const float* w_t1 = (const float*)d_in[5];
    const float* b_t1 = (const float*)d_in[6];
    const float* w_c1 = (const float*)d_in[7];
    const float* b_c1 = (const float*)d_in[8];
    const float* g1   = (const float*)d_in[9];
    const float* be1  = (const float*)d_in[10];
    const float* w_t2 = (const float*)d_in[11];
    const float* b_t2 = (const float*)d_in[12];
    const float* w_c2 = (const float*)d_in[13];
    const float* b_c2 = (const float*)d_in[14];
    const float* g2   = (const float*)d_in[15];
    const float* be2  = (const float*)d_in[16];
    float* out = (float*)d_out;

    __half* pX0h; cudaGetSymbolAddress((void**)&pX0h, g_X0h);
    __half* pX1h; cudaGetSymbolAddress((void**)&pX1h, g_X1h);
    float*  pY;   cudaGetSymbolAddress((void**)&pY,   g_Y);
    __half* pW1h; cudaGetSymbolAddress((void**)&pW1h, g_W1h);
    __half* pW2h; cudaGetSymbolAddress((void**)&pW2h, g_W2h);
    float*  pb1;  cudaGetSymbolAddress((void**)&pb1,  g_bias1);
    float*  pb2;  cudaGetSymbolAddress((void**)&pb2,  g_bias2);
    float*  pS1;  cudaGetSymbolAddress((void**)&pS1,  g_s1);
    float*  pS2;  cudaGetSymbolAddress((void**)&pS2,  g_s2);

    const int GEMM_SMEM = 4 * STAGE_B + 1024;   // 99328 bytes
    cudaFuncSetAttribute(gemm_hmma_kernel<CIN>, cudaFuncAttributeMaxDynamicSharedMemorySize, GEMM_SMEM);
    cudaFuncSetAttribute(gemm_hmma_kernel<MM>,  cudaFuncAttributeMaxDynamicSharedMemorySize, GEMM_SMEM);

    // ---- prep ----
    te_bias_kernel<<<BB, CIN>>>(t_embed, w_t1, b_t1, w_c1, b_c1, w_t2, b_t2, w_c2, b_c2);
    knn_kernel<<<dim3(NN / 256, BB), 256>>>(xyz1, xyz2);
    transpose_p2<<<dim3(SS / 32, C2 / 32, BB), dim3(32, 8)>>>(points2);
    convw_kernel<<<(MM * CIN + MM * MM + 255) / 256, 256>>>(w_c1, w_c2);
    tr_p1_kernel<<<dim3(NN / 32, C1 / 32, BB), dim3(32, 8)>>>(points1);
    interp_kernel<<<PP / 32, 256>>>();

    // ---- layer 1 ----
    cudaMemsetAsync(pS1, 0, MM * sizeof(float));
    cudaMemsetAsync(pS2, 0, MM * sizeof(float));
    gemm_hmma_kernel<CIN><<<PP / 128, 256, GEMM_SMEM>>>(pX0h, pW1h, pb1, pY);
    bn_finish_kernel<<<1, 256>>>(g1, be1);
    bn_act_h_kernel<<<PP * MM / 1024, 256>>>(pY, pX1h);

    // ---- layer 2 ----
    cudaMemsetAsync(pS1, 0, MM * sizeof(float));
    cudaMemsetAsync(pS2, 0, MM * sizeof(float));
    gemm_hmma_kernel<MM><<<PP / 128, 256, GEMM_SMEM>>>(pX1h, pW2h, pb2, pY);
    bn_finish_kernel<<<1, 256>>>(g2, be2);
    bn_out_kernel<<<dim3(PP / 32, MM / 32), dim3(32, 8)>>>(pY, out);
}

// round 5
// speedup vs baseline: 1.7472x; 1.0101x over previous
#include <cuda_runtime.h>
#include <cuda_fp16.h>
#include <math.h>
#include <stdint.h>

// ---------------- problem constants ----------------
#define BB   8
#define NN   8192
#define SS   2048
#define C1   128
#define C2   256
#define TT   256
#define CIN  384
#define PP   65536      // B*N
#define MM   256        // output channels of both convs

// ---------------- device scratch ----------------
__device__ __half g_X0h[(size_t)PP * CIN];   // conv1 input, point-major [p][384] fp16
__device__ __half g_X1h[(size_t)PP * MM];    // conv2 input, point-major [p][256] fp16
__device__ __half g_Yh [(size_t)PP * MM];    // preact (both layers), point-major fp16
__device__ __half g_W1h[MM * CIN];
__device__ __half g_W2h[MM * MM];
__device__ float  g_p2t[(size_t)BB * SS * C2];  // points2 transposed (b,s,c) fp32
__device__ int    g_idx[PP * 3];
__device__ float  g_wt [PP * 3];
__device__ float  g_bias1[BB * MM];
__device__ float  g_bias2[BB * MM];
__device__ float  g_s1[MM], g_s2[MM];        // BN accumulators (atomic)
__device__ float  g_sc[MM], g_sh[MM];        // BN scale/shift

__device__ __forceinline__ float gelu_exact(float x) {
    return 0.5f * x * (1.0f + erff(x * 0.70710678118654752440f));
}

__device__ __forceinline__ uint32_t smem_u32(const void* p) {
    return (uint32_t)__cvta_generic_to_shared(p);
}

#define CP_ASYNC16(dst, src) \
    asm volatile("cp.async.cg.shared.global [%0], [%1], 16;\n" :: "r"(dst), "l"(src))
#define CP_COMMIT() asm volatile("cp.async.commit_group;\n" ::: "memory")
#define CP_WAIT2()  asm volatile("cp.async.wait_group 2;\n" ::: "memory")

__device__ __forceinline__ void ldmatrix_x4(uint32_t& r0, uint32_t& r1,
                                            uint32_t& r2, uint32_t& r3, uint32_t addr) {
    asm volatile("ldmatrix.sync.aligned.m8n8.x4.shared.b16 {%0,%1,%2,%3}, [%4];"
                 : "=r"(r0), "=r"(r1), "=r"(r2), "=r"(r3) : "r"(addr));
}

__device__ __forceinline__ void mma16816(float* d, const uint32_t* a, const uint32_t* b) {
    asm volatile("mma.sync.aligned.m16n8k16.row.col.f32.f16.f16.f32 "
                 "{%0,%1,%2,%3}, {%4,%5,%6,%7}, {%8,%9}, {%0,%1,%2,%3};"
                 : "+f"(d[0]), "+f"(d[1]), "+f"(d[2]), "+f"(d[3])
                 : "r"(a[0]), "r"(a[1]), "r"(a[2]), "r"(a[3]), "r"(b[0]), "r"(b[1]));
}

// ---------------- time-conditioning biases ----------------
__global__ void te_bias_kernel(const float* __restrict__ t_embed,
                               const float* __restrict__ w_t1, const float* __restrict__ b_t1,
                               const float* __restrict__ w_c1, const float* __restrict__ b_c1,
                               const float* __restrict__ w_t2, const float* __restrict__ b_t2,
                               const float* __restrict__ w_c2, const float* __restrict__ b_c2) {
    __shared__ float ge[TT];
    __shared__ float te1[CIN];
    __shared__ float te2[MM];
    int b = blockIdx.x;
    int t = threadIdx.x;          // 0..383
    if (t < TT) ge[t] = gelu_exact(t_embed[b * TT + t]);
    __syncthreads();
    {
        float a = b_t1[t];
        const float* w = w_t1 + (size_t)t * TT;
        #pragma unroll 4
        for (int c = 0; c < TT; c++) a += ge[c] * w[c];
        te1[t] = a;
    }
    if (t < MM) {
        float a = b_t2[t];
        const float* w = w_t2 + (size_t)t * TT;
        #pragma unroll 4
        for (int c = 0; c < TT; c++) a += ge[c] * w[c];
        te2[t] = a;
    }
    __syncthreads();
    if (t < MM) {
        float a = b_c1[t];
        const float* w = w_c1 + (size_t)t * CIN;
        #pragma unroll 4
        for (int c = 0; c < CIN; c++) a += te1[c] * w[c];
        g_bias1[b * MM + t] = a;

        float a2 = b_c2[t];
        const float* w2 = w_c2 + (size_t)t * MM;
        #pragma unroll 4
        for (int c = 0; c < MM; c++) a2 += te2[c] * w2[c];
        g_bias2[b * MM + t] = a2;
    }
}

// ---------------- 3-NN (fused distance + top-3) ----------------
__global__ __launch_bounds__(256) void knn_kernel(const float* __restrict__ xyz1,
                                                  const float* __restrict__ xyz2) {
    __shared__ float4 sp[SS];
    int b = blockIdx.y;
    int n = blockIdx.x * 256 + threadIdx.x;
    const float* p2 = xyz2 + (size_t)b * SS * 3;
    for (int s = threadIdx.x; s < SS; s += 256) {
        float x = p2[s * 3 + 0], y = p2[s * 3 + 1], z = p2[s * 3 + 2];
        sp[s] = make_float4(x, y, z, x * x + y * y + z * z);
    }
    __syncthreads();
    const float* p1 = xyz1 + ((size_t)b * NN + n) * 3;
    float px = p1[0], py = p1[1], pz = p1[2];
    float n1 = px * px + py * py + pz * pz;

    float d0 = 1e30f, d1 = 1e30f, d2 = 1e30f;
    int   i0 = 0, i1 = 0, i2 = 0;
    for (int s = 0; s < SS; s++) {
        float4 q = sp[s];
        float t = fmaf(px, q.x, fmaf(py, q.y, pz * q.z));
        float d = n1 + q.w - 2.0f * t;
        if (d < d2) {
            if (d < d0)      { d2 = d1; i2 = i1; d1 = d0; i1 = i0; d0 = d; i0 = s; }
            else if (d < d1) { d2 = d1; i2 = i1; d1 = d; i1 = s; }
            else             { d2 = d; i2 = s; }
        }
    }
    float r0 = 1.0f / (d0 + 1e-8f);
    float r1 = 1.0f / (d1 + 1e-8f);
    float r2 = 1.0f / (d2 + 1e-8f);
    float inv = 1.0f / (r0 + r1 + r2);
    int base = (b * NN + n) * 3;
    g_idx[base + 0] = i0; g_idx[base + 1] = i1; g_idx[base + 2] = i2;
    g_wt [base + 0] = r0 * inv; g_wt [base + 1] = r1 * inv; g_wt [base + 2] = r2 * inv;
}

// ---------------- transpose points2 (B,C2,S) -> (B,S,C2) fp32 ----------------
__global__ void transpose_p2(const float* __restrict__ points2) {
    __shared__ float tile[32][33];
    int b  = blockIdx.z;
    int s0 = blockIdx.x * 32;
    int c0 = blockIdx.y * 32;
    for (int i = threadIdx.y; i < 32; i += 8)
        tile[i][threadIdx.x] =
            points2[((size_t)b * C2 + (c0 + i)) * SS + s0 + threadIdx.x];
    __syncthreads();
    for (int i = threadIdx.y; i < 32; i += 8)
        g_p2t[((size_t)b * SS + (s0 + i)) * C2 + c0 + threadIdx.x] = tile[threadIdx.x][i];
}

// ---------------- weights fp32 -> fp16 (both layers, one launch) -----------
__global__ void convw_kernel(const float* __restrict__ w1, const float* __restrict__ w2) {
    int i = blockIdx.x * 256 + threadIdx.x;
    if (i < MM * CIN) g_W1h[i] = __float2half_rn(w1[i]);
    else {
        int j = i - MM * CIN;
        if (j < MM * MM) g_W2h[j] = __float2half_rn(w2[j]);
    }
}

// ---------------- points1 (b,c,n) -> X0h[p][c], c in [0,128), fp16 ----------
__global__ void tr_p1_kernel(const float* __restrict__ points1) {
    __shared__ float tile[32][33];
    int b  = blockIdx.z;
    int n0 = blockIdx.x * 32;
    int c0 = blockIdx.y * 32;
    int tx = threadIdx.x, ty = threadIdx.y;
    for (int i = ty; i < 32; i += 8)
        tile[i][tx] = points1[((size_t)(b * C1 + c0 + i) << 13) + n0 + tx];
    __syncthreads();
    for (int i = ty; i < 32; i += 8)
        g_X0h[(size_t)(b * NN + n0 + i) * CIN + c0 + tx] = __float2half_rn(tile[tx][i]);
}

// ---------------- 3-NN interpolation -> X0h[p][128..384), fp16 -------------
__global__ __launch_bounds__(256) void interp_kernel() {
    __shared__ int   sidx[32 * 3];
    __shared__ float swt [32 * 3];
    int p0 = blockIdx.x * 32;
    int b  = p0 >> 13;
    int t  = threadIdx.x;   // channel 0..255
    if (t < 96) { sidx[t] = g_idx[p0 * 3 + t]; swt[t] = g_wt[p0 * 3 + t]; }
    __syncthreads();
    const float* base = g_p2t + (size_t)b * SS * C2;
    #pragma unroll 4
    for (int pp = 0; pp < 32; pp++) {
        const float* r0 = base + (size_t)sidx[pp * 3 + 0] * C2;
        const float* r1 = base + (size_t)sidx[pp * 3 + 1] * C2;
        const float* r2 = base + (size_t)sidx[pp * 3 + 2] * C2;
        float v = swt[pp * 3 + 0] * r0[t] + swt[pp * 3 + 1] * r1[t]
                + swt[pp * 3 + 2] * r2[t];
        g_X0h[(size_t)(p0 + pp) * CIN + C1 + t] = __float2half_rn(v);
    }
}

// ---------------- HMMA GEMM: Yh[p][o] = fp16(sum_k Xh[p][k]*Wh[o][k] + bias)
// CTA: 128 points x 256 channels, BK=32, 4-stage cp.async pipeline,
// 16 warps (2x8), warp tile 64x32. Fused fp32 BN partial-stat accumulation.
// SMEM XOR swizzle: 64B rows of 4x16B chunks, chunk ^= (row & 3).
#define STAGE_B 24576      // bytes per stage: A 8192 + B 16384
template<int K>
__global__ __launch_bounds__(512, 1) void gemm_hmma_kernel(
    const __half* __restrict__ Xh,      // [P][K]
    const __half* __restrict__ Wh,      // [256][K]
    const float* __restrict__ colbias,  // [B][256]
    __half* __restrict__ Yh)            // [P][256]
{
    extern __shared__ __align__(16) char smem[];
    const uint32_t sbase = smem_u32(smem);
    float* sbias = (float*)(smem + 4 * STAGE_B);

    const int tid = threadIdx.x;
    const int lane = tid & 31;
    const int wid = tid >> 5;          // 0..15
    const int warp_m = wid & 1;        // 0..1
    const int warp_n = wid >> 1;       // 0..7
    const int p0 = blockIdx.x * 128;

    if (tid < 256) sbias[tid] = colbias[(p0 >> 13) * MM + tid];

    // chunk loader: A 512 + B 1024 16B-chunks per stage, 512 threads
    auto load_stage = [&](int t) {
        const uint32_t base = sbase + (uint32_t)(t & 3) * STAGE_B;
        const int k0 = t * 32;
        {
            int row = tid >> 2, ch = tid & 3;
            uint32_t doff = ((uint32_t)(row * 32 + ((ch ^ (row & 3)) * 8))) * 2;
            CP_ASYNC16(base + doff, Xh + (size_t)(p0 + row) * K + k0 + ch * 8);
        }
        #pragma unroll
        for (int i = 0; i < 2; i++) {
            int idx = tid + i * 512;
            int row = idx >> 2, ch = idx & 3;
            uint32_t doff = 8192u + ((uint32_t)(row * 32 + ((ch ^ (row & 3)) * 8))) * 2;
            CP_ASYNC16(base + doff, Wh + (size_t)row * K + k0 + ch * 8);
        }
        CP_COMMIT();
    };

    float acc[4][4][4];
    #pragma unroll
    for (int mt = 0; mt < 4; mt++)
        #pragma unroll
        for (int nt = 0; nt < 4; nt++)
            #pragma unroll
            for (int e = 0; e < 4; e++) acc[mt][nt][e] = 0.0f;

    const int a_row_off = (lane & 7) + ((lane >> 3) & 1) * 8;
    const int a_ch_off  = lane >> 4;
    const int b_mat     = lane >> 3;
    const int b_row_off = ((b_mat >> 1) * 8) + (lane & 7);
    const int b_ch_off  = b_mat & 1;

    constexpr int NT = K / 32;
    load_stage(0); load_stage(1); load_stage(2);
    CP_WAIT2();
    __syncthreads();

    for (int t = 0; t < NT; t++) {
        const uint32_t sA = sbase + (uint32_t)(t & 3) * STAGE_B;
        const uint32_t sB = sA + 8192u;
        #pragma unroll
        for (int ks = 0; ks < 2; ks++) {
            uint32_t a[4][4];
            #pragma unroll
            for (int mt = 0; mt < 4; mt++) {
                int row = warp_m * 64 + mt * 16 + a_row_off;
                int ch  = ks * 2 + a_ch_off;
                uint32_t addr = sA + ((uint32_t)(row * 32 + ((ch ^ (row & 3)) * 8))) * 2;
                ldmatrix_x4(a[mt][0], a[mt][1], a[mt][2], a[mt][3], addr);
            }
            uint32_t b[4][2];
            #pragma unroll
            for (int nt2 = 0; nt2 < 2; nt2++) {
                int row = warp_n * 32 + nt2 * 16 + b_row_off;
                int ch  = ks * 2 + b_ch_off;
                uint32_t addr = sB + ((uint32_t)(row * 32 + ((ch ^ (row & 3)) * 8))) * 2;
                ldmatrix_x4(b[nt2 * 2][0], b[nt2 * 2][1],
                            b[nt2 * 2 + 1][0], b[nt2 * 2 + 1][1], addr);
            }
            #pragma unroll
            for (int mt = 0; mt < 4; mt++)
                #pragma unroll
                for (int nt = 0; nt < 4; nt++)
                    mma16816(acc[mt][nt], a[mt], b[nt]);
        }
        if (t + 3 < NT) load_stage(t + 3); else CP_COMMIT();
        CP_WAIT2();
        __syncthreads();
    }

    // epilogue: bias add, fp32 BN partial sums, fp16 store
    float ps[8], ps2v[8];
    #pragma unroll
    for (int j = 0; j < 8; j++) { ps[j] = 0.0f; ps2v[j] = 0.0f; }

    const int r_base = p0 + warp_m * 64 + (lane >> 2);
    #pragma unroll
    for (int nt = 0; nt < 4; nt++) {
        int col = warp_n * 32 + nt * 8 + 2 * (lane & 3);
        float b0 = sbias[col], b1 = sbias[col + 1];
        #pragma unroll
        for (int mt = 0; mt < 4; mt++) {
            int r0 = r_base + mt * 16;
            float v00 = acc[mt][nt][0] + b0, v01 = acc[mt][nt][1] + b1;
            float v10 = acc[mt][nt][2] + b0, v11 = acc[mt][nt][3] + b1;
            *(__half2*)(Yh + (size_t)r0 * MM + col)       = __floats2half2_rn(v00, v01);
            *(__half2*)(Yh + (size_t)(r0 + 8) * MM + col) = __floats2half2_rn(v10, v11);
            ps  [nt * 2]     += v00 + v10;
            ps  [nt * 2 + 1] += v01 + v11;
            ps2v[nt * 2]     += v00 * v00 + v10 * v10;
            ps2v[nt * 2 + 1] += v01 * v01 + v11 * v11;
        }
    }
    #pragma unroll
    for (int off = 4; off < 32; off <<= 1) {
        #pragma unroll
        for (int j = 0; j < 8; j++) {
            ps[j]   += __shfl_xor_sync(0xffffffffu, ps[j],   off);
            ps2v[j] += __shfl_xor_sync(0xffffffffu, ps2v[j], off);
        }
    }
    if (lane < 4) {
        #pragma unroll
        for (int nt = 0; nt < 4; nt++) {
            int col = warp_n * 32 + nt * 8 + 2 * lane;
            atomicAdd(&g_s1[col],     ps[nt * 2]);
            atomicAdd(&g_s1[col + 1], ps[nt * 2 + 1]);
            atomicAdd(&g_s2[col],     ps2v[nt * 2]);
            atomicAdd(&g_s2[col + 1], ps2v[nt * 2 + 1]);
        }
    }
}

__global__ void bn_finish_kernel(const float* __restrict__ gamma,
                                 const float* __restrict__ beta) {
    int o = threadIdx.x;
    float m = g_s1[o] * (1.0f / PP);
    float v = g_s2[o] * (1.0f / PP) - m * m;
    float sc = gamma[o] * rsqrtf(v + 1e-5f);
    g_sc[o] = sc;
    g_sh[o] = beta[o] - m * sc;
}

// ---------------- BN + GELU -> fp16 point-major (layer 1) ----------------
__global__ __launch_bounds__(256) void bn_act_h_kernel(const __half* __restrict__ Yh,
                                                       __half* __restrict__ Xh) {
    __shared__ float ssc[MM], ssh[MM];
    if (threadIdx.x < MM) { ssc[threadIdx.x] = g_sc[threadIdx.x]; ssh[threadIdx.x] = g_sh[threadIdx.x]; }
    __syncthreads();
    size_t i4 = (size_t)blockIdx.x * 256 + threadIdx.x;
    size_t i = i4 * 4;
    int o = (int)(i & (MM - 1));
    uint2 raw = *(const uint2*)(Yh + i);
    __half2 h01 = *(__half2*)&raw.x;
    __half2 h23 = *(__half2*)&raw.y;
    float a0 = gelu_exact(fmaf(__low2float(h01),  ssc[o + 0], ssh[o + 0]));
    float a1 = gelu_exact(fmaf(__high2float(h01), ssc[o + 1], ssh[o + 1]));
    float a2 = gelu_exact(fmaf(__low2float(h23),  ssc[o + 2], ssh[o + 2]));
    float a3 = gelu_exact(fmaf(__high2float(h23), ssc[o + 3], ssh[o + 3]));
    __half2* dst = (__half2*)(Xh + i);
    dst[0] = __floats2half2_rn(a0, a1);
    dst[1] = __floats2half2_rn(a2, a3);
}

// ---------------- BN + GELU + transpose (p,o) -> out (b,o,n) --------------
__global__ void bn_out_kernel(const __half* __restrict__ Yh, float* __restrict__ out) {
    __shared__ float tile[32][33];
    int p0 = blockIdx.x * 32;
    int o0 = blockIdx.y * 32;
    int tx = threadIdx.x, ty = threadIdx.y;
    for (int i = ty; i < 32; i += 8) {
        int o = o0 + tx;
        float v = __half2float(Yh[(size_t)(p0 + i) * MM + o]);
        tile[i][tx] = gelu_exact(fmaf(v, g_sc[o], g_sh[o]));
    }
    __syncthreads();
    int b  = p0 >> 13;
    int n0 = p0 & (NN - 1);
    for (int i = ty; i < 32; i += 8)
        out[((size_t)(b * MM + o0 + i) << 13) + n0 + tx] = tile[tx][i];
}

// ---------------- launcher ----------------
extern "C" void kernel_launch(void* const* d_in, const int* in_sizes, int n_in,
                              void* d_out, int out_size) {
    const float* xyz1    = (const float*)d_in[0];
    const float* xyz2    = (const float*)d_in[1];
    const float* points1 = (const float*)d_in[2];
    const float* points2 = (const float*)d_in[3];
    const float* t_embed = (const float*)d_in[4];
    const float* w_t1 = (const float*)d_in[5];
    const float* b_t1 = (const float*)d_in[6];
    const float* w_c1 = (const float*)d_in[7];
    const float* b_c1 = (const float*)d_in[8];
    const float* g1   = (const float*)d_in[9];
    const float* be1  = (const float*)d_in[10];
    const float* w_t2 = (const float*)d_in[11];
    const float* b_t2 = (const float*)d_in[12];
    const float* w_c2 = (const float*)d_in[13];
    const float* b_c2 = (const float*)d_in[14];
    const float* g2   = (const float*)d_in[15];
    const float* be2  = (const float*)d_in[16];
    float* out = (float*)d_out;

    __half* pX0h; cudaGetSymbolAddress((void**)&pX0h, g_X0h);
    __half* pX1h; cudaGetSymbolAddress((void**)&pX1h, g_X1h);
    __half* pYh;  cudaGetSymbolAddress((void**)&pYh,  g_Yh);
    __half* pW1h; cudaGetSymbolAddress((void**)&pW1h, g_W1h);
    __half* pW2h; cudaGetSymbolAddress((void**)&pW2h, g_W2h);
    float*  pb1;  cudaGetSymbolAddress((void**)&pb1,  g_bias1);
    float*  pb2;  cudaGetSymbolAddress((void**)&pb2,  g_bias2);
    float*  pS1;  cudaGetSymbolAddress((void**)&pS1,  g_s1);
    float*  pS2;  cudaGetSymbolAddress((void**)&pS2,  g_s2);

    const int GEMM_SMEM = 4 * STAGE_B + 1024;   // 99328 bytes
    cudaFuncSetAttribute(gemm_hmma_kernel<CIN>, cudaFuncAttributeMaxDynamicSharedMemorySize, GEMM_SMEM);
    cudaFuncSetAttribute(gemm_hmma_kernel<MM>,  cudaFuncAttributeMaxDynamicSharedMemorySize, GEMM_SMEM);

    // ---- prep ----
    te_bias_kernel<<<BB, CIN>>>(t_embed, w_t1, b_t1, w_c1, b_c1, w_t2, b_t2, w_c2, b_c2);
    knn_kernel<<<dim3(NN / 256, BB), 256>>>(xyz1, xyz2);
    transpose_p2<<<dim3(SS / 32, C2 / 32, BB), dim3(32, 8)>>>(points2);
    convw_kernel<<<(MM * CIN + MM * MM + 255) / 256, 256>>>(w_c1, w_c2);
    tr_p1_kernel<<<dim3(NN / 32, C1 / 32, BB), dim3(32, 8)>>>(points1);
    interp_kernel<<<PP / 32, 256>>>();

    // ---- layer 1 ----
    cudaMemsetAsync(pS1, 0, MM * sizeof(float));
    cudaMemsetAsync(pS2, 0, MM * sizeof(float));
    gemm_hmma_kernel<CIN><<<PP / 128, 512, GEMM_SMEM>>>(pX0h, pW1h, pb1, pYh);
    bn_finish_kernel<<<1, 256>>>(g1, be1);
    bn_act_h_kernel<<<PP * MM / 1024, 256>>>(pYh, pX1h);

    // ---- layer 2 ----
    cudaMemsetAsync(pS1, 0, MM * sizeof(float));
    cudaMemsetAsync(pS2, 0, MM * sizeof(float));
    gemm_hmma_kernel<MM><<<PP / 128, 512, GEMM_SMEM>>>(pX1h, pW2h, pb2, pYh);
    bn_finish_kernel<<<1, 256>>>(g2, be2);
    bn_out_kernel<<<dim3(PP / 32, MM / 32), dim3(32, 8)>>>(pYh, out);
}